// round 2
// baseline (speedup 1.0000x reference)
#include <cuda_runtime.h>

// Problem constants
#define NE   39
#define ND   16
#define NDFF 64
#define NB   32768
#define OPC  6

// Bucketing
#define CAP     2048       // slots per expert bucket (mean count ~840, sd ~29)
#define CCHUNK  8          // chunks per expert in compute grid
#define CTH     128        // compute block threads

// Per-expert smem slot layout (floats): Wv[256] Wo[256] W1[1024] b1[64] W2[1024] b2[16]
#define WPE     2640
#define OFF_WV  0
#define OFF_WO  256
#define OFF_W1  512
#define OFF_B1  1536
#define OFF_W2  1600
#define OFF_B2  2624

__device__ int g_cursor[NE];
__device__ int g_rows[NE * CAP];

typedef unsigned long long u64;

// ---- packed f32x2 helpers (Blackwell-only FFMA2 path, PTX-only per SASS docs) ----
__device__ __forceinline__ u64 pk2(float lo, float hi) {
    u64 r; asm("mov.b64 %0,{%1,%2};" : "=l"(r) : "f"(lo), "f"(hi)); return r;
}
__device__ __forceinline__ void up2(u64 v, float& lo, float& hi) {
    asm("mov.b64 {%0,%1},%2;" : "=f"(lo), "=f"(hi) : "l"(v));
}
__device__ __forceinline__ void fm2(u64& d, u64 a, u64 b) {
    asm("fma.rn.f32x2 %0,%1,%2,%0;" : "+l"(d) : "l"(a), "l"(b));
}
__device__ __forceinline__ u64 ad2(u64 a, u64 b) {
    u64 r; asm("add.rn.f32x2 %0,%1,%2;" : "=l"(r) : "l"(a), "l"(b)); return r;
}
__device__ __forceinline__ float hsum(u64 v) { float a, b; up2(v, a, b); return a + b; }
__device__ __forceinline__ float sigf(float x) { return 1.0f / (1.0f + __expf(-x)); }

// ---- K0: zero bucket cursors (graph replays, so must reset every call) ----
__global__ void k_zero() {
    int t = threadIdx.x;
    if (t < NE) g_cursor[t] = 0;
}

// ---- K1: smem-aggregated scatter of row ids into per-expert buckets ----
__global__ void k_scatter(const float* __restrict__ state) {
    __shared__ int hc[NE];
    __shared__ int hb[NE];
    int t = threadIdx.x;
    if (t < NE) hc[t] = 0;
    __syncthreads();
    int b = blockIdx.x * blockDim.x + t;
    int e = 0, lr = 0;
    if (b < NB) {
        e = (int)state[b * ND + OPC];
        e = min(NE - 1, max(0, e));
        lr = atomicAdd(&hc[e], 1);           // local rank within block
    }
    __syncthreads();
    if (t < NE && hc[t] > 0) hb[t] = atomicAdd(&g_cursor[t], hc[t]);  // reserve base
    __syncthreads();
    if (b < NB) g_rows[e * CAP + hb[e] + lr] = b;
}

__device__ __forceinline__ void cp4(float* dst, const float* __restrict__ src, int n4) {
    for (int i = threadIdx.x; i < n4; i += CTH)
        reinterpret_cast<float4*>(dst)[i] = __ldg(reinterpret_cast<const float4*>(src) + i);
}

// ---- K2: expert-centric compute. block = (center expert, chunk). ----
// Per row: out = sum_{e in {op-1,op,op+1}} gate(op-e) * x2(b,e)
// where x2 = x1 + FFN(LN(x1)), x1 = state + Wo@(Wv@LN(state))  (softmax over size-1 axis == 1,
// so Q/K/scores are dead code; |diff|>=2 gates are ~1e-13 and dropped).
__global__ __launch_bounds__(CTH) void k_compute(
    const float* __restrict__ state,
    const float* __restrict__ Wv, const float* __restrict__ Wo,
    const float* __restrict__ W1, const float* __restrict__ b1,
    const float* __restrict__ W2, const float* __restrict__ b2,
    float* __restrict__ out)
{
    __shared__ __align__(16) float sw[3 * WPE];
    const int ec = blockIdx.x;

    // Stage weights for experts {ec-1, ec, ec+1}
    for (int s = 0; s < 3; s++) {
        int e = ec - 1 + s;
        if (e < 0 || e >= NE) continue;
        float* dst = sw + s * WPE;
        cp4(dst + OFF_WV, Wv + e * 256,  64);
        cp4(dst + OFF_WO, Wo + e * 256,  64);
        cp4(dst + OFF_W1, W1 + e * 1024, 256);
        cp4(dst + OFF_B1, b1 + e * 64,   16);
        cp4(dst + OFF_W2, W2 + e * 1024, 256);
        cp4(dst + OFF_B2, b2 + e * 16,   4);
    }
    __syncthreads();

    const int cnt = g_cursor[ec];
    const int len = (cnt + CCHUNK - 1) / CCHUNK;
    const int lo0 = blockIdx.y * len;
    const int hi0 = min(cnt, lo0 + len);

    for (int i = lo0 + threadIdx.x; i < hi0; i += CTH) {
        const int row = g_rows[ec * CAP + i];

        float st[16];
        {
            const float4* sp = reinterpret_cast<const float4*>(state + row * ND);
            #pragma unroll
            for (int q = 0; q < 4; q++) {
                float4 v = __ldg(sp + q);
                st[4 * q] = v.x; st[4 * q + 1] = v.y; st[4 * q + 2] = v.z; st[4 * q + 3] = v.w;
            }
        }

        // LN1
        float m = 0.f;
        #pragma unroll
        for (int d = 0; d < 16; d++) m += st[d];
        m *= 0.0625f;
        float var = 0.f;
        #pragma unroll
        for (int d = 0; d < 16; d++) { float t = st[d] - m; var += t * t; }
        var *= 0.0625f;
        float rs = rsqrtf(var + 1e-5f);
        u64 xnp[8];
        #pragma unroll
        for (int p = 0; p < 8; p++)
            xnp[p] = pk2((st[2 * p] - m) * rs, (st[2 * p + 1] - m) * rs);

        float acc[16];
        #pragma unroll
        for (int d = 0; d < 16; d++) acc[d] = 0.f;

        for (int s = 0; s < 3; s++) {
            int e = ec - 1 + s;
            if (e < 0 || e >= NE) continue;
            // all rows in this bucket have opcode == ec exactly, so diff = ec - e = 1 - s
            float diff = 1.0f - (float)s;
            float g = sigf((diff + 0.5f) * 20.f) * sigf((-diff + 0.5f) * 20.f);
            const float* W = sw + s * WPE;

            // V = Wv @ xn
            float V[16];
            {
                const ulonglong2* w = reinterpret_cast<const ulonglong2*>(W + OFF_WV);
                #pragma unroll
                for (int o = 0; o < 16; o++) {
                    u64 a = 0ull, b = 0ull;
                    #pragma unroll
                    for (int p = 0; p < 4; p++) {
                        ulonglong2 wv2 = w[o * 4 + p];
                        fm2(a, wv2.x, xnp[2 * p]);
                        fm2(b, wv2.y, xnp[2 * p + 1]);
                    }
                    V[o] = hsum(ad2(a, b));
                }
            }
            u64 Vp[8];
            #pragma unroll
            for (int p = 0; p < 8; p++) Vp[p] = pk2(V[2 * p], V[2 * p + 1]);

            // x1 = state + Wo @ V
            float x1[16];
            {
                const ulonglong2* w = reinterpret_cast<const ulonglong2*>(W + OFF_WO);
                #pragma unroll
                for (int j = 0; j < 16; j++) {
                    u64 a = 0ull, b = 0ull;
                    #pragma unroll
                    for (int p = 0; p < 4; p++) {
                        ulonglong2 wv2 = w[j * 4 + p];
                        fm2(a, wv2.x, Vp[2 * p]);
                        fm2(b, wv2.y, Vp[2 * p + 1]);
                    }
                    x1[j] = st[j] + hsum(ad2(a, b));
                }
            }

            // LN2
            float m2 = 0.f;
            #pragma unroll
            for (int d = 0; d < 16; d++) m2 += x1[d];
            m2 *= 0.0625f;
            float v2 = 0.f;
            #pragma unroll
            for (int d = 0; d < 16; d++) { float t = x1[d] - m2; v2 += t * t; }
            v2 *= 0.0625f;
            float rs2 = rsqrtf(v2 + 1e-5f);
            u64 yp[8];
            #pragma unroll
            for (int p = 0; p < 8; p++)
                yp[p] = pk2((x1[2 * p] - m2) * rs2, (x1[2 * p + 1] - m2) * rs2);

            // h = silu(W1 @ xn2 + b1), kept as 32 packed pairs in registers
            u64 hp[32];
            {
                const ulonglong2* w = reinterpret_cast<const ulonglong2*>(W + OFF_W1);
                const float* B1 = W + OFF_B1;
                #pragma unroll
                for (int f = 0; f < 64; f += 2) {
                    u64 a0 = 0ull, a1 = 0ull, c0 = 0ull, c1 = 0ull;
                    #pragma unroll
                    for (int p = 0; p < 4; p++) {
                        ulonglong2 wa = w[f * 4 + p];
                        fm2(a0, wa.x, yp[2 * p]);
                        fm2(a1, wa.y, yp[2 * p + 1]);
                        ulonglong2 wb = w[(f + 1) * 4 + p];
                        fm2(c0, wb.x, yp[2 * p]);
                        fm2(c1, wb.y, yp[2 * p + 1]);
                    }
                    float y0 = hsum(ad2(a0, a1)) + B1[f];
                    float y1 = hsum(ad2(c0, c1)) + B1[f + 1];
                    hp[f >> 1] = pk2(y0 * sigf(y0), y1 * sigf(y1));
                }
            }

            // ffn = W2 @ h + b2 ; acc += g * (x1 + ffn)
            {
                const ulonglong2* w = reinterpret_cast<const ulonglong2*>(W + OFF_W2);
                const float* B2 = W + OFF_B2;
                #pragma unroll
                for (int j = 0; j < 16; j++) {
                    u64 a = 0ull, b = 0ull;
                    #pragma unroll
                    for (int p = 0; p < 16; p++) {
                        ulonglong2 wv2 = w[j * 16 + p];
                        fm2(a, wv2.x, hp[2 * p]);
                        fm2(b, wv2.y, hp[2 * p + 1]);
                    }
                    float ffn = hsum(ad2(a, b)) + B2[j];
                    acc[j] = fmaf(g, x1[j] + ffn, acc[j]);
                }
            }
        }

        float4* op = reinterpret_cast<float4*>(out + row * ND);
        #pragma unroll
        for (int q = 0; q < 4; q++) {
            float4 v;
            v.x = acc[4 * q]; v.y = acc[4 * q + 1]; v.z = acc[4 * q + 2]; v.w = acc[4 * q + 3];
            op[q] = v;
        }
    }
}

extern "C" void kernel_launch(void* const* d_in, const int* in_sizes, int n_in,
                              void* d_out, int out_size) {
    (void)in_sizes; (void)n_in; (void)out_size;
    const float* state = (const float*)d_in[0];
    // d_in[1]=Wq, d_in[2]=Wk are dead (softmax over a size-1 axis is identically 1)
    const float* Wv = (const float*)d_in[3];
    const float* Wo = (const float*)d_in[4];
    const float* W1 = (const float*)d_in[5];
    const float* b1 = (const float*)d_in[6];
    const float* W2 = (const float*)d_in[7];
    const float* b2 = (const float*)d_in[8];
    float* out = (float*)d_out;

    k_zero<<<1, 64>>>();
    k_scatter<<<NB / 256, 256>>>(state);
    k_compute<<<dim3(NE, CCHUNK), CTH>>>(state, Wv, Wo, W1, b1, W2, b2, out);
}

// round 3
// speedup vs baseline: 1.0269x; 1.0269x over previous
#include <cuda_runtime.h>

// Problem constants
#define NE   39
#define ND   16
#define NDFF 64
#define NB   32768
#define OPC  6

// Bucketing
#define CAP     2048
#define CCHUNK  8
#define CTH     128

// Per-expert smem slot layout (floats): Wv[256] Wo[256] W1[1024] b1[64] W2t[1024] b2[16]
// W2t is W2 TRANSPOSED: W2t[f][j] = W2[j][f], so row f (16 floats) is contiguous.
#define WPE     2640
#define OFF_WV  0
#define OFF_WO  256
#define OFF_W1  512
#define OFF_B1  1536
#define OFF_W2T 1600
#define OFF_B2  2624

__device__ int g_cursor[NE];
__device__ int g_rows[NE * CAP];

typedef unsigned long long u64;

// ---- packed f32x2 helpers (Blackwell FFMA2 path, PTX-only) ----
__device__ __forceinline__ u64 pk2(float lo, float hi) {
    u64 r; asm("mov.b64 %0,{%1,%2};" : "=l"(r) : "f"(lo), "f"(hi)); return r;
}
__device__ __forceinline__ void up2(u64 v, float& lo, float& hi) {
    asm("mov.b64 {%0,%1},%2;" : "=f"(lo), "=f"(hi) : "l"(v));
}
__device__ __forceinline__ void fm2(u64& d, u64 a, u64 b) {
    asm("fma.rn.f32x2 %0,%1,%2,%0;" : "+l"(d) : "l"(a), "l"(b));
}
__device__ __forceinline__ u64 ad2(u64 a, u64 b) {
    u64 r; asm("add.rn.f32x2 %0,%1,%2;" : "=l"(r) : "l"(a), "l"(b)); return r;
}
__device__ __forceinline__ float hsum(u64 v) { float a, b; up2(v, a, b); return a + b; }
__device__ __forceinline__ float sigf(float x) { return 1.0f / (1.0f + __expf(-x)); }

// ---- K0: zero bucket cursors (graph replays -> must reset every call) ----
__global__ void k_zero() {
    int t = threadIdx.x;
    if (t < NE) g_cursor[t] = 0;
}

// ---- K1: smem-aggregated scatter of row ids into per-expert buckets ----
__global__ void k_scatter(const float* __restrict__ state) {
    __shared__ int hc[NE];
    __shared__ int hb[NE];
    int t = threadIdx.x;
    if (t < NE) hc[t] = 0;
    __syncthreads();
    int b = blockIdx.x * blockDim.x + t;
    int e = 0, lr = 0;
    if (b < NB) {
        e = (int)state[b * ND + OPC];
        e = min(NE - 1, max(0, e));
        lr = atomicAdd(&hc[e], 1);
    }
    __syncthreads();
    if (t < NE && hc[t] > 0) hb[t] = atomicAdd(&g_cursor[t], hc[t]);
    __syncthreads();
    if (b < NB) g_rows[e * CAP + hb[e] + lr] = b;
}

__device__ __forceinline__ void cp4(float* dst, const float* __restrict__ src, int n4) {
    for (int i = threadIdx.x; i < n4; i += CTH)
        reinterpret_cast<float4*>(dst)[i] = __ldg(reinterpret_cast<const float4*>(src) + i);
}

// ---- K2: expert-centric compute. Streaming FFN (no hp[32] array -> low reg pressure). ----
// out = sum_{e in {op-1,op,op+1}} gate(op-e) * x2(b,e)
// x2 = x1 + FFN(LN(x1)); x1 = state + Wo@(Wv@LN(state)); softmax over size-1 axis == 1,
// so Q/K/scores are dead; |diff|>=2 gates (~1e-13) dropped.
__global__ __launch_bounds__(CTH) void k_compute(
    const float* __restrict__ state,
    const float* __restrict__ Wv, const float* __restrict__ Wo,
    const float* __restrict__ W1, const float* __restrict__ b1,
    const float* __restrict__ W2, const float* __restrict__ b2,
    float* __restrict__ out)
{
    __shared__ __align__(16) float sw[3 * WPE];
    const int ec = blockIdx.x;

    // Stage weights for experts {ec-1, ec, ec+1}; W2 transposed on the fly.
    for (int s = 0; s < 3; s++) {
        int e = ec - 1 + s;
        if (e < 0 || e >= NE) continue;
        float* dst = sw + s * WPE;
        cp4(dst + OFF_WV, Wv + e * 256,  64);
        cp4(dst + OFF_WO, Wo + e * 256,  64);
        cp4(dst + OFF_W1, W1 + e * 1024, 256);
        cp4(dst + OFF_B1, b1 + e * 64,   16);
        cp4(dst + OFF_B2, b2 + e * 16,   4);
        // transpose W2 [16 j][64 f] -> W2t [64 f][16 j]
        {
            const float4* src = reinterpret_cast<const float4*>(W2 + e * 1024);
            float* t = dst + OFF_W2T;
            for (int i4 = threadIdx.x; i4 < 256; i4 += CTH) {
                int j = i4 >> 4;          // 0..15
                int f = (i4 & 15) << 2;   // 0,4,..,60
                float4 v = __ldg(src + i4);
                t[(f + 0) * 16 + j] = v.x;
                t[(f + 1) * 16 + j] = v.y;
                t[(f + 2) * 16 + j] = v.z;
                t[(f + 3) * 16 + j] = v.w;
            }
        }
    }
    __syncthreads();

    const int cnt = g_cursor[ec];
    const int len = (cnt + CCHUNK - 1) / CCHUNK;
    const int lo0 = blockIdx.y * len;
    const int hi0 = min(cnt, lo0 + len);

    for (int i = lo0 + threadIdx.x; i < hi0; i += CTH) {
        const int row = g_rows[ec * CAP + i];

        float st[16];
        {
            const float4* sp = reinterpret_cast<const float4*>(state + row * ND);
            #pragma unroll
            for (int q = 0; q < 4; q++) {
                float4 v = __ldg(sp + q);
                st[4 * q] = v.x; st[4 * q + 1] = v.y; st[4 * q + 2] = v.z; st[4 * q + 3] = v.w;
            }
        }

        // LN1
        float m = 0.f;
        #pragma unroll
        for (int d = 0; d < 16; d++) m += st[d];
        m *= 0.0625f;
        float var = 0.f;
        #pragma unroll
        for (int d = 0; d < 16; d++) { float t = st[d] - m; var += t * t; }
        var *= 0.0625f;
        float rs = rsqrtf(var + 1e-5f);
        u64 xnp[8];
        #pragma unroll
        for (int p = 0; p < 8; p++)
            xnp[p] = pk2((st[2 * p] - m) * rs, (st[2 * p + 1] - m) * rs);

        u64 accp[8];
        #pragma unroll
        for (int p = 0; p < 8; p++) accp[p] = 0ull;

        for (int s = 0; s < 3; s++) {
            int e = ec - 1 + s;
            if (e < 0 || e >= NE) continue;
            // rows in this bucket have opcode == ec exactly -> diff = 1 - s
            float diff = 1.0f - (float)s;
            float g = sigf((diff + 0.5f) * 20.f) * sigf((-diff + 0.5f) * 20.f);
            u64 g2 = pk2(g, g);
            const float* W = sw + s * WPE;

            // V = Wv @ xn
            u64 Vp[8];
            {
                const ulonglong2* w = reinterpret_cast<const ulonglong2*>(W + OFF_WV);
                #pragma unroll
                for (int o = 0; o < 16; o += 2) {
                    u64 a0 = 0ull, a1 = 0ull, c0 = 0ull, c1 = 0ull;
                    #pragma unroll
                    for (int p = 0; p < 4; p++) {
                        ulonglong2 wa = w[o * 4 + p];
                        fm2(a0, wa.x, xnp[2 * p]);
                        fm2(a1, wa.y, xnp[2 * p + 1]);
                        ulonglong2 wb = w[(o + 1) * 4 + p];
                        fm2(c0, wb.x, xnp[2 * p]);
                        fm2(c1, wb.y, xnp[2 * p + 1]);
                    }
                    Vp[o >> 1] = pk2(hsum(ad2(a0, a1)), hsum(ad2(c0, c1)));
                }
            }

            // x1 = state + Wo @ V
            float x1[16];
            {
                const ulonglong2* w = reinterpret_cast<const ulonglong2*>(W + OFF_WO);
                #pragma unroll
                for (int j = 0; j < 16; j++) {
                    u64 a = 0ull, b = 0ull;
                    #pragma unroll
                    for (int p = 0; p < 4; p++) {
                        ulonglong2 wv2 = w[j * 4 + p];
                        fm2(a, wv2.x, Vp[2 * p]);
                        fm2(b, wv2.y, Vp[2 * p + 1]);
                    }
                    x1[j] = st[j] + hsum(ad2(a, b));
                }
            }

            // LN2
            float m2 = 0.f;
            #pragma unroll
            for (int d = 0; d < 16; d++) m2 += x1[d];
            m2 *= 0.0625f;
            float v2 = 0.f;
            #pragma unroll
            for (int d = 0; d < 16; d++) { float t = x1[d] - m2; v2 += t * t; }
            v2 *= 0.0625f;
            float rs2 = rsqrtf(v2 + 1e-5f);
            u64 yp[8];
            #pragma unroll
            for (int p = 0; p < 8; p++)
                yp[p] = pk2((x1[2 * p] - m2) * rs2, (x1[2 * p + 1] - m2) * rs2);

            // Streaming FFN: ffn_j = b2_j + sum_f silu(W1[f]@y + b1[f]) * W2t[f][j]
            // 8 packed (j-pair) accumulators; h_f never stored as an array.
            u64 ffnp[8];
            {
                const u64* b2p = reinterpret_cast<const u64*>(W + OFF_B2);
                #pragma unroll
                for (int p = 0; p < 8; p++) ffnp[p] = b2p[p];
            }
            {
                const ulonglong2* w1 = reinterpret_cast<const ulonglong2*>(W + OFF_W1);
                const ulonglong2* w2t = reinterpret_cast<const ulonglong2*>(W + OFF_W2T);
                const float* B1 = W + OFF_B1;
                #pragma unroll 4
                for (int f = 0; f < 64; f++) {
                    u64 a = 0ull, b = 0ull;
                    #pragma unroll
                    for (int p = 0; p < 4; p++) {
                        ulonglong2 wv2 = w1[f * 4 + p];
                        fm2(a, wv2.x, yp[2 * p]);
                        fm2(b, wv2.y, yp[2 * p + 1]);
                    }
                    float y = hsum(ad2(a, b)) + B1[f];
                    float h = y * sigf(y);
                    u64 h2 = pk2(h, h);
                    ulonglong2 r0 = w2t[f * 4 + 0];
                    ulonglong2 r1 = w2t[f * 4 + 1];
                    ulonglong2 r2 = w2t[f * 4 + 2];
                    ulonglong2 r3 = w2t[f * 4 + 3];
                    fm2(ffnp[0], h2, r0.x); fm2(ffnp[1], h2, r0.y);
                    fm2(ffnp[2], h2, r1.x); fm2(ffnp[3], h2, r1.y);
                    fm2(ffnp[4], h2, r2.x); fm2(ffnp[5], h2, r2.y);
                    fm2(ffnp[6], h2, r3.x); fm2(ffnp[7], h2, r3.y);
                }
            }

            // acc += g * (x1 + ffn)
            #pragma unroll
            for (int p = 0; p < 8; p++) {
                u64 x1p = pk2(x1[2 * p], x1[2 * p + 1]);
                fm2(accp[p], g2, ad2(x1p, ffnp[p]));
            }
        }

        float4* op = reinterpret_cast<float4*>(out + row * ND);
        #pragma unroll
        for (int q = 0; q < 4; q++) {
            float a0, a1, a2, a3;
            up2(accp[2 * q], a0, a1);
            up2(accp[2 * q + 1], a2, a3);
            float4 v; v.x = a0; v.y = a1; v.z = a2; v.w = a3;
            op[q] = v;
        }
    }
}

extern "C" void kernel_launch(void* const* d_in, const int* in_sizes, int n_in,
                              void* d_out, int out_size) {
    (void)in_sizes; (void)n_in; (void)out_size;
    const float* state = (const float*)d_in[0];
    // d_in[1]=Wq, d_in[2]=Wk dead (softmax over size-1 axis == 1)
    const float* Wv = (const float*)d_in[3];
    const float* Wo = (const float*)d_in[4];
    const float* W1 = (const float*)d_in[5];
    const float* b1 = (const float*)d_in[6];
    const float* W2 = (const float*)d_in[7];
    const float* b2 = (const float*)d_in[8];
    float* out = (float*)d_out;

    k_zero<<<1, 64>>>();
    k_scatter<<<NB / 256, 256>>>(state);
    k_compute<<<dim3(NE, CCHUNK), CTH>>>(state, Wv, Wo, W1, b1, W2, b2, out);
}